// round 13
// baseline (speedup 1.0000x reference)
#include <cuda_runtime.h>
#include <cuda_bf16.h>
#include <math.h>
#include <stdint.h>

// Problem constants
#define B_   1024
#define T_   64
#define H_   512
#define V_   1024
#define GEN_ 100
#define H4_  2048
#define NGATES 128
#define NHEAD  128
#define NTOT   256
#define BH_   (B_ * H_)
#define NK_   (H4_ * H_)

// gates smem: 2 buffers x 6 tiles x (128 rows x 64B) = 98304; tok at end
#define TILE_B   8192
#define BUF_B    (6 * TILE_B)        // 49152
#define SM_TOK   98304
#define SMEM_DYN 98816
// head view offsets
#define SMH_Z1D  32768
#define SMH_LSE  (32768 + 6656)

typedef unsigned long long ull;

// Persistent state (device globals — no allocation allowed)
__device__ float d_hbuf[2][BH_];          // fp32 hidden (for head)
__device__ float d_c[BH_];                // cell state
__device__ float d_bias[H4_];             // b_ih + b_hh
__device__ float d_W2T[GEN_ * V_];        // W2 transposed
__device__ float d_WihT[V_ * H4_];        // W_ih transposed [tok][4H]
__device__ __nv_bfloat16 d_hb[3][2][BH_]; // h bf16x3 splits, ping-pong
__device__ __nv_bfloat16 d_wb[3][NK_];    // Whh bf16x3 splits, row-permuted
__device__ int   d_tok[B_];
__device__ unsigned d_bar_count, d_bar_gen, d_tok_cnt, d_tok_gen;

__device__ __forceinline__ float sigm(float x) { return 1.0f / (1.0f + expf(-x)); }

__device__ __forceinline__ ull pack2(float a, float b) {
    ull r; asm("mov.b64 %0, {%1, %2};" : "=l"(r) : "f"(a), "f"(b)); return r;
}
__device__ __forceinline__ void ffma2(ull& d, ull a, ull b) {
    asm("fma.rn.f32x2 %0, %1, %2, %0;" : "+l"(d) : "l"(a), "l"(b));
}
__device__ __forceinline__ float2 unp2(ull v) {
    float2 f; asm("mov.b64 {%0, %1}, %2;" : "=f"(f.x), "=f"(f.y) : "l"(v)); return f;
}
__device__ __forceinline__ uint32_t smem_to_u32(const void* p) {
    uint32_t a;
    asm("{ .reg .u64 t; cvta.to.shared.u64 t, %1; cvt.u32.u64 %0, t; }" : "=r"(a) : "l"(p));
    return a;
}
__device__ __forceinline__ void ldsm_x4(uint32_t& r0, uint32_t& r1, uint32_t& r2, uint32_t& r3,
                                        uint32_t addr) {
    asm volatile("ldmatrix.sync.aligned.m8n8.x4.shared.b16 {%0,%1,%2,%3}, [%4];"
                 : "=r"(r0), "=r"(r1), "=r"(r2), "=r"(r3) : "r"(addr));
}
__device__ __forceinline__ void mma16816(float* c, uint32_t a0, uint32_t a1, uint32_t a2,
                                         uint32_t a3, uint32_t b0, uint32_t b1) {
    asm volatile("mma.sync.aligned.m16n8k16.row.col.f32.bf16.bf16.f32 "
                 "{%0,%1,%2,%3}, {%4,%5,%6,%7}, {%8,%9}, {%0,%1,%2,%3};"
                 : "+f"(c[0]), "+f"(c[1]), "+f"(c[2]), "+f"(c[3])
                 : "r"(a0), "r"(a1), "r"(a2), "r"(a3), "r"(b0), "r"(b1));
}
__device__ __forceinline__ void cp16(uint32_t dst, const void* src) {
    asm volatile("cp.async.cg.shared.global [%0], [%1], 16;" :: "r"(dst), "l"(src));
}
#define CP_COMMIT() asm volatile("cp.async.commit_group;" ::: "memory")

// swizzled byte offset within a 128x64B tile: row r (0..127), seg s (0..3, 16B each)
__device__ __forceinline__ uint32_t swz(int r, int s) {
    return (uint32_t)(r * 64 + ((s * 16) ^ ((r & 6) << 3)));
}

// Stage barrier across all NTOT blocks.
__device__ __forceinline__ void stage_barrier() {
    __threadfence();
    __syncthreads();
    if (threadIdx.x == 0) {
        const unsigned gen = *((volatile unsigned*)&d_bar_gen);
        if (atomicAdd(&d_bar_count, 1u) == NTOT - 1) {
            d_bar_count = 0;
            __threadfence();
            *((volatile unsigned*)&d_bar_gen) = gen + 1;
        } else {
            while (*((volatile unsigned*)&d_bar_gen) == gen) { __nanosleep(32); }
        }
    }
    __syncthreads();
}

__device__ __forceinline__ void split3(float x, __nv_bfloat16& a, __nv_bfloat16& b, __nv_bfloat16& c) {
    a = __float2bfloat16(x);
    float r = x - __bfloat162float(a);
    b = __float2bfloat16(r);
    float r2 = r - __bfloat162float(b);
    c = __float2bfloat16(r2);
}

// ---------------------------------------------------------------------------
// init / transposes / weight split
// ---------------------------------------------------------------------------
__global__ void init_kernel(const float* __restrict__ input,
                            const float* __restrict__ onehots,
                            const float* __restrict__ Wh, const float* __restrict__ bh,
                            const float* __restrict__ Wc, const float* __restrict__ bc,
                            const float* __restrict__ b_ih, const float* __restrict__ b_hh)
{
    const int b = blockIdx.x;
    const int tid = threadIdx.x;
    const float xv = input[b];

    if (b == 0 && tid == 0) {
        d_bar_count = 0; d_bar_gen = 0; d_tok_cnt = 0; d_tok_gen = 0;
    }
    for (int i = tid; i < H_; i += 256) {
        const float hv = xv * Wh[i] + bh[i];
        d_hbuf[0][b * H_ + i] = hv;
        d_c[b * H_ + i]       = xv * Wc[i] + bc[i];
        __nv_bfloat16 s0, s1, s2;
        split3(hv, s0, s1, s2);
        d_hb[0][0][b * H_ + i] = s0;
        d_hb[1][0][b * H_ + i] = s1;
        d_hb[2][0][b * H_ + i] = s2;
    }
    if (b < H4_ / 256) {
        const int j = b * 256 + tid;
        d_bias[j] = b_ih[j] + b_hh[j];
    }
    const float* oh = onehots + (size_t)b * T_ * V_;
    for (int v = tid; v < V_; v += 256)
        if (oh[v] > 0.5f) d_tok[b] = v;
}

__global__ void transpose_w2_kernel(const float* __restrict__ W2)
{
    const int k = blockIdx.x;
    for (int v = threadIdx.x; v < V_; v += 256)
        d_W2T[k * V_ + v] = __ldg(&W2[(size_t)v * GEN_ + k]);
}

__global__ void transpose_wih_kernel(const float* __restrict__ Wih)
{
    __shared__ float tile[32][33];
    const int j0 = blockIdx.x * 32;
    const int v0 = blockIdx.y * 32;
    const int tx = threadIdx.x & 31;
    const int ty = threadIdx.x >> 5;
    for (int r = ty; r < 32; r += 8)
        tile[r][tx] = Wih[(size_t)(j0 + r) * V_ + v0 + tx];
    __syncthreads();
    for (int r = ty; r < 32; r += 8)
        d_WihT[(size_t)(v0 + r) * H4_ + j0 + tx] = tile[tx][r];
}

// Whh bf16x3 split, row-permuted: p = gby*128 + q*32 + hh  <-  orig row q*512 + gby*32 + hh
__global__ void split_whh_kernel(const float* __restrict__ Whh)
{
    const int p = blockIdx.x;
    const int gby = p >> 7, j = p & 127, q = j >> 5, hh = j & 31;
    const int o = q * H_ + gby * 32 + hh;
    for (int k = threadIdx.x; k < H_; k += 256) {
        __nv_bfloat16 s0, s1, s2;
        split3(Whh[(size_t)o * H_ + k], s0, s1, s2);
        d_wb[0][(size_t)p * H_ + k] = s0;
        d_wb[1][(size_t)p * H_ + k] = s1;
        d_wb[2][(size_t)p * H_ + k] = s2;
    }
}

// ---------------------------------------------------------------------------
// Pipelined persistent kernel: gates (HMMA bf16x3) || head. 2 CTAs/SM.
// ---------------------------------------------------------------------------
extern __shared__ __align__(1024) char smemc[];

__global__ void __launch_bounds__(256, 2)
lstm_pipeline_kernel(const float* __restrict__ W1, const float* __restrict__ b1,
                     const float* __restrict__ b2, float* __restrict__ out)
{
    const int tid = threadIdx.x;
    const int blk = blockIdx.x;

    if (blk < NGATES) {
        // ==================== GATES ROLE (HMMA) ====================
        const int gbx = blk & 7;
        const int gby = blk >> 3;
        const int b0g = gbx * 128;          // batch tile base
        const int p0  = gby * 128;          // permuted gate-row tile base
        const int h0g = gby * 32;           // hcol base
        const uint32_t smem_u32 = smem_to_u32(smemc);
        const int wid = tid >> 5, lane = tid & 31;
        const int wm = wid & 1, wn = wid >> 1;

        // ---- precomputed lane-invariant ldmatrix offsets ----
        // A: lanes g=l>>3: row = wm*64 + (g&1)*8 + (l&7); seg = 2ks + (g>>1)
        const int rowA = wm * 64 + ((lane >> 3) & 1) * 8 + (lane & 7);
        uint32_t a0k[2];
#pragma unroll
        for (int ks = 0; ks < 2; ks++)
            a0k[ks] = swz(rowA, 2 * ks + (lane >> 4));
        // B: row = wn*32 + nbp*16 + ((l>>4)&1)*8 + (l&7); seg = 2ks + ((l>>3)&1)
        uint32_t b0k[2][2];
#pragma unroll
        for (int ks = 0; ks < 2; ks++)
#pragma unroll
            for (int nbp = 0; nbp < 2; nbp++) {
                const int rowB = wn * 32 + nbp * 16 + ((lane >> 4) & 1) * 8 + (lane & 7);
                b0k[ks][nbp] = swz(rowB, 2 * ks + ((lane >> 3) & 1));
            }

        // ---- loader geometry: thread covers row r=tid>>1, segs {2(tid&1), +1}, all 6 tiles
        const int lr = tid >> 1;
        const int ls0 = 2 * (tid & 1);
        uint32_t dOff[6][2];
#pragma unroll
        for (int tl = 0; tl < 6; tl++)
#pragma unroll
            for (int q = 0; q < 2; q++)
                dOff[tl][q] = (uint32_t)(tl * TILE_B) + swz(lr, ls0 + q);
        const size_t aRowOff = (size_t)(b0g + lr) * 1024 + ls0 * 16;   // bytes into split array
        const size_t bRowOff = (size_t)(p0 + lr) * 1024 + ls0 * 16;

        for (int t = 0; t < T_; t++) {
            const int par = t & 1;
            const char* aB[3] = { (const char*)d_hb[0][par], (const char*)d_hb[1][par],
                                  (const char*)d_hb[2][par] };
            const char* bB[3] = { (const char*)d_wb[0], (const char*)d_wb[1],
                                  (const char*)d_wb[2] };

            float acc[4][4][4];
#pragma unroll
            for (int i = 0; i < 4; i++)
#pragma unroll
                for (int j = 0; j < 4; j++)
#pragma unroll
                    for (int e = 0; e < 4; e++) acc[i][j][e] = 0.f;

            // prologue: load chunk 0 into buffer 0
            {
                const size_t co = 0;
#pragma unroll
                for (int tl = 0; tl < 3; tl++)
#pragma unroll
                    for (int q = 0; q < 2; q++) {
                        cp16(smem_u32 + dOff[tl][q],     aB[tl] + aRowOff + q * 16 + co);
                        cp16(smem_u32 + dOff[tl + 3][q], bB[tl] + bRowOff + q * 16 + co);
                    }
                CP_COMMIT();
            }

            for (int c = 0; c < 16; c++) {
                if (c < 15) {
                    const uint32_t db = smem_u32 + ((c + 1) & 1) * BUF_B;
                    const size_t co = (size_t)(c + 1) * 64;
#pragma unroll
                    for (int tl = 0; tl < 3; tl++)
#pragma unroll
                        for (int q = 0; q < 2; q++) {
                            cp16(db + dOff[tl][q],     aB[tl] + aRowOff + q * 16 + co);
                            cp16(db + dOff[tl + 3][q], bB[tl] + bRowOff + q * 16 + co);
                        }
                    CP_COMMIT();
                    asm volatile("cp.async.wait_group 1;" ::: "memory");
                } else {
                    asm volatile("cp.async.wait_group 0;" ::: "memory");
                }
                __syncthreads();

                const uint32_t bb = smem_u32 + (c & 1) * BUF_B;
#pragma unroll
                for (int ks = 0; ks < 2; ks++) {
#pragma unroll
                    for (int sa = 0; sa < 3; sa++) {
                        uint32_t A[4][4];
#pragma unroll
                        for (int mb = 0; mb < 4; mb++)
                            ldsm_x4(A[mb][0], A[mb][1], A[mb][2], A[mb][3],
                                    bb + sa * TILE_B + mb * 1024 + a0k[ks]);
#pragma unroll
                        for (int sb = 0; sb < 3 - sa; sb++) {
                            uint32_t Bf[2][4];
#pragma unroll
                            for (int nbp = 0; nbp < 2; nbp++)
                                ldsm_x4(Bf[nbp][0], Bf[nbp][1], Bf[nbp][2], Bf[nbp][3],
                                        bb + (3 + sb) * TILE_B + b0k[ks][nbp]);
#pragma unroll
                            for (int mb = 0; mb < 4; mb++)
#pragma unroll
                                for (int nbp = 0; nbp < 2; nbp++) {
                                    mma16816(acc[mb][nbp * 2],
                                             A[mb][0], A[mb][1], A[mb][2], A[mb][3],
                                             Bf[nbp][0], Bf[nbp][1]);
                                    mma16816(acc[mb][nbp * 2 + 1],
                                             A[mb][0], A[mb][1], A[mb][2], A[mb][3],
                                             Bf[nbp][2], Bf[nbp][3]);
                                }
                        }
                    }
                }
                __syncthreads();
            }

            // ---- stage accumulators to smem: gs[p_local][b_local] (128x128 f32)
            {
                float* gs = (float*)smemc;
                const int r_ = lane >> 2, c2 = (lane & 3) * 2;
#pragma unroll
                for (int mb = 0; mb < 4; mb++)
#pragma unroll
                    for (int nb = 0; nb < 4; nb++) {
                        const int bl = wm * 64 + mb * 16 + r_;
                        const int pl = wn * 32 + nb * 8 + c2;
                        gs[pl * 128 + bl]             = acc[mb][nb][0];
                        gs[(pl + 1) * 128 + bl]       = acc[mb][nb][1];
                        gs[pl * 128 + bl + 8]         = acc[mb][nb][2];
                        gs[(pl + 1) * 128 + bl + 8]   = acc[mb][nb][3];
                    }
            }

            // token sync + staging
            if (t > 0 && tid == 0) {
                while (*((volatile unsigned*)&d_tok_gen) < (unsigned)t) { __nanosleep(32); }
            }
            __syncthreads();
            if (tid < 128) ((int*)(smemc + SM_TOK))[tid] = __ldcg(&d_tok[b0g + tid]);
            __syncthreads();

            // ---- fused LSTM cell epilogue
            {
                const float* gs = (const float*)smemc;
                float* hout = d_hbuf[par ^ 1];
#pragma unroll
                for (int jj = 0; jj < 16; jj++) {
                    const int idx = tid + 256 * jj;
                    const int bl = idx & 127;
                    const int hh = idx >> 7;
                    const int b = b0g + bl;
                    const int hcol = h0g + hh;
                    const int tok = ((const int*)(smemc + SM_TOK))[bl];
                    const float* WT = d_WihT + (size_t)tok * H4_;
                    const float gi = gs[(0 * 32 + hh) * 128 + bl] + __ldg(&WT[0 * H_ + hcol]) + __ldg(&d_bias[0 * H_ + hcol]);
                    const float gf = gs[(1 * 32 + hh) * 128 + bl] + __ldg(&WT[1 * H_ + hcol]) + __ldg(&d_bias[1 * H_ + hcol]);
                    const float gq = gs[(2 * 32 + hh) * 128 + bl] + __ldg(&WT[2 * H_ + hcol]) + __ldg(&d_bias[2 * H_ + hcol]);
                    const float go = gs[(3 * 32 + hh) * 128 + bl] + __ldg(&WT[3 * H_ + hcol]) + __ldg(&d_bias[3 * H_ + hcol]);
                    const float co = d_c[(size_t)b * H_ + hcol];
                    const float cn = sigm(gf) * co + sigm(gi) * tanhf(gq);
                    const float hn = sigm(go) * tanhf(cn);
                    d_c[(size_t)b * H_ + hcol] = cn;
                    hout[(size_t)b * H_ + hcol] = hn;
                    __nv_bfloat16 s0, s1, s2;
                    split3(hn, s0, s1, s2);
                    d_hb[0][par ^ 1][(size_t)b * H_ + hcol] = s0;
                    d_hb[1][par ^ 1][(size_t)b * H_ + hcol] = s1;
                    d_hb[2][par ^ 1][(size_t)b * H_ + hcol] = s2;
                }
            }
            stage_barrier();
        }
        stage_barrier();   // final stage (head step 63 runs alone)

    } else {
        // ==================== HEAD ROLE ====================
        float* sbuf = (float*)smemc;                            // 8x1024 (h, then z2)
        float2 (*z1d)[104] = (float2 (*)[104])(smemc + SMH_Z1D);
        float* lse_s = (float*)(smemc + SMH_LSE);

        const int hid = blk - NGATES;
        const int b0h = hid * 8;
        const int w = tid >> 5, lane = tid & 31;

        stage_barrier();   // stage 0: gates step 0 runs alone

        for (int t = 0; t < T_; t++) {
            const float* __restrict__ hbuf = d_hbuf[(t + 1) & 1];

            {
                float4* sb4 = (float4*)sbuf;
                const float4* hb4 = (const float4*)(hbuf + (size_t)b0h * H_);
                for (int i = tid; i < 8 * H_ / 4; i += 256) sb4[i] = __ldcg(hb4 + i);
            }
            __syncthreads();

            // z1: warp per output column g
            for (int g = w; g < GEN_; g += 8) {
                float a[8];
#pragma unroll
                for (int bi = 0; bi < 8; bi++) a[bi] = 0.f;
                const float4* wp = (const float4*)(W1 + (size_t)g * H_);
#pragma unroll
                for (int p = 0; p < 4; p++) {
                    const float4 wv = __ldg(wp + p * 32 + lane);
#pragma unroll
                    for (int bi = 0; bi < 8; bi++) {
                        const float4 hv = *(const float4*)&sbuf[bi * H_ + (p * 32 + lane) * 4];
                        a[bi] += wv.x * hv.x + wv.y * hv.y + wv.z * hv.z + wv.w * hv.w;
                    }
                }
#pragma unroll
                for (int bi = 0; bi < 8; bi++) {
#pragma unroll
                    for (int off = 16; off; off >>= 1)
                        a[bi] += __shfl_down_sync(0xffffffffu, a[bi], off);
                }
                if (lane == 0) {
                    const float bv = b1[g];
#pragma unroll
                    for (int bi = 0; bi < 8; bi++) {
                        const float z = fmaxf(a[bi] + bv, 0.f);
                        z1d[bi][g] = make_float2(z, z);
                    }
                }
            }
            __syncthreads();

            // z2: thread owns 4 consecutive v; coalesced W2T rows; FFMA2
            float (*z2s)[1024] = (float (*)[1024])sbuf;
            {
                const int v0 = tid * 4;
                ull acc[8][2];
                {
                    const float4 bv = *(const float4*)(b2 + v0);
                    const ull bl = pack2(bv.x, bv.y), bh2 = pack2(bv.z, bv.w);
#pragma unroll
                    for (int bi = 0; bi < 8; bi++) { acc[bi][0] = bl; acc[bi][1] = bh2; }
                }
#pragma unroll 5
                for (int k = 0; k < GEN_; k++) {
                    const float4 wv = __ldcg((const float4*)(d_W2T + k * V_ + v0));
                    const ull wl = pack2(wv.x, wv.y), wh = pack2(wv.z, wv.w);
#pragma unroll
                    for (int bi = 0; bi < 8; bi++) {
                        const ull z = *(const ull*)&z1d[bi][k];
                        ffma2(acc[bi][0], z, wl);
                        ffma2(acc[bi][1], z, wh);
                    }
                }
#pragma unroll
                for (int bi = 0; bi < 8; bi++) {
                    const float2 lo = unp2(acc[bi][0]);
                    const float2 hi = unp2(acc[bi][1]);
                    *(float4*)&z2s[bi][v0] = make_float4(lo.x, lo.y, hi.x, hi.y);
                }
            }
            __syncthreads();

            // argmax + LSE; publish tok ASAP
            {
                float m = -3.0e38f; int mi = 0;
                for (int v = lane; v < V_; v += 32) {
                    const float x = z2s[w][v];
                    if (x > m) { m = x; mi = v; }
                }
#pragma unroll
                for (int off = 16; off; off >>= 1) {
                    const float om  = __shfl_down_sync(0xffffffffu, m, off);
                    const int   omi = __shfl_down_sync(0xffffffffu, mi, off);
                    if (om > m || (om == m && omi < mi)) { m = om; mi = omi; }
                }
                m  = __shfl_sync(0xffffffffu, m, 0);
                mi = __shfl_sync(0xffffffffu, mi, 0);

                float s = 0.f;
                for (int v = lane; v < V_; v += 32) s += expf(z2s[w][v] - m);
#pragma unroll
                for (int off = 16; off; off >>= 1) s += __shfl_down_sync(0xffffffffu, s, off);

                if (lane == 0) {
                    lse_s[w] = m + logf(s);
                    d_tok[b0h + w] = mi;
                }
            }
            __syncthreads();
            __threadfence();
            if (tid == 0) {
                if (atomicAdd(&d_tok_cnt, 1u) == NHEAD - 1) {
                    d_tok_cnt = 0;
                    __threadfence();
                    *((volatile unsigned*)&d_tok_gen) = (unsigned)(t + 1);
                }
            }

            float* orow = out + (size_t)t * B_ * V_ + (size_t)b0h * V_;
            for (int i = tid; i < 8 * V_ / 4; i += 256) {
                const int bi = i >> 8;
                float4 v4 = *(const float4*)&z2s[bi][(i & 255) * 4];
                const float l = lse_s[bi];
                v4.x -= l; v4.y -= l; v4.z -= l; v4.w -= l;
                *(float4*)&orow[i * 4] = v4;
            }
            stage_barrier();
        }
    }
}

// ---------------------------------------------------------------------------
// kernel_launch
// ---------------------------------------------------------------------------
extern "C" void kernel_launch(void* const* d_in, const int* in_sizes, int n_in,
                              void* d_out, int out_size)
{
    const float* input   = (const float*)d_in[0];
    const float* onehots = (const float*)d_in[1];
    const float* Wh   = (const float*)d_in[4];
    const float* bh   = (const float*)d_in[5];
    const float* Wc   = (const float*)d_in[6];
    const float* bc   = (const float*)d_in[7];
    const float* W_ih = (const float*)d_in[8];
    const float* W_hh = (const float*)d_in[9];
    const float* b_ih = (const float*)d_in[10];
    const float* b_hh = (const float*)d_in[11];
    const float* W1   = (const float*)d_in[12];
    const float* b1   = (const float*)d_in[13];
    const float* W2   = (const float*)d_in[14];
    const float* b2   = (const float*)d_in[15];
    float* out = (float*)d_out;

    cudaFuncSetAttribute(lstm_pipeline_kernel,
                         cudaFuncAttributeMaxDynamicSharedMemorySize, SMEM_DYN);

    init_kernel<<<B_, 256>>>(input, onehots, Wh, bh, Wc, bc, b_ih, b_hh);
    transpose_w2_kernel<<<GEN_, 256>>>(W2);
    {
        dim3 g(H4_ / 32, V_ / 32);
        transpose_wih_kernel<<<g, 256>>>(W_ih);
    }
    split_whh_kernel<<<H4_, 256>>>(W_hh);
    lstm_pipeline_kernel<<<NTOT, 256, SMEM_DYN>>>(W1, b1, b2, out);
}

// round 14
// speedup vs baseline: 1.6409x; 1.6409x over previous
#include <cuda_runtime.h>
#include <math.h>
#include <stdint.h>

// Problem constants
#define B_   1024
#define T_   64
#define H_   512
#define V_   1024
#define GEN_ 100
#define H4_  2048
#define NGATES 128
#define NHEAD  128
#define NTOT   256
#define BH_   (B_ * H_)

// K split between gates CTA and its paired head CTA
#define KSPLIT 384
#define NCH_G  24     // gates chunks of 16 (k 0..383)
#define NCH_H  8      // head partial chunks of 16 (k 384..511)

// smem layout: gates = 2 double-buffered 16x132 tiles (h, w) + tok
#define SM_TOK   33792
#define SMEM_DYN 39552
// head view
#define SMH_Z1D  32768
#define SMH_LSE  (32768 + 6656)

typedef unsigned long long ull;

// Persistent state (device globals — no allocation allowed)
__device__ float d_hbuf[2][BH_];       // fp32 hidden (ping-pong)
__device__ float d_c[BH_];             // cell state
__device__ float d_bias[H4_];          // b_ih + b_hh
__device__ float d_W2T[GEN_ * V_];     // W2 transposed
__device__ float d_WihT[V_ * H4_];     // W_ih transposed [tok][4H]
__device__ float d_part[NGATES * 128 * 128];  // per-tile K-partial [tile][b*128+p]
__device__ unsigned d_pflag[NGATES];   // partial-ready flag (== step+1)
__device__ int   d_tok[B_];
__device__ unsigned d_bar_count, d_bar_gen, d_tok_cnt, d_tok_gen;

__device__ __forceinline__ float sigm(float x) { return 1.0f / (1.0f + expf(-x)); }

__device__ __forceinline__ ull dup2(float x) {
    ull r; asm("mov.b64 %0, {%1, %1};" : "=l"(r) : "f"(x)); return r;
}
__device__ __forceinline__ ull pack2(float a, float b) {
    ull r; asm("mov.b64 %0, {%1, %2};" : "=l"(r) : "f"(a), "f"(b)); return r;
}
__device__ __forceinline__ void ffma2(ull& d, ull a, ull b) {
    asm("fma.rn.f32x2 %0, %1, %2, %0;" : "+l"(d) : "l"(a), "l"(b));
}
__device__ __forceinline__ float2 unp2(ull v) {
    float2 f; asm("mov.b64 {%0, %1}, %2;" : "=f"(f.x), "=f"(f.y) : "l"(v)); return f;
}

// Stage barrier across all NTOT blocks (all co-resident, 2 CTAs/SM).
__device__ __forceinline__ void stage_barrier() {
    __threadfence();
    __syncthreads();
    if (threadIdx.x == 0) {
        const unsigned gen = *((volatile unsigned*)&d_bar_gen);
        if (atomicAdd(&d_bar_count, 1u) == NTOT - 1) {
            d_bar_count = 0;
            __threadfence();
            *((volatile unsigned*)&d_bar_gen) = gen + 1;
        } else {
            while (*((volatile unsigned*)&d_bar_gen) == gen) { __nanosleep(32); }
        }
    }
    __syncthreads();
}

// ---------------------------------------------------------------------------
// Shared FFMA2 GEMM slice: acc2[u][q] += h[b0g+ty*8+u, k] * Whh[q*512+h0g+tx*2{+1}, k]
// over k in [kbase, kbase + nchunks*16). Double-buffered smem, 1 sync/chunk.
// ---------------------------------------------------------------------------
__device__ __forceinline__ void gemm_slice(ull (&acc2)[8][4],
                                           const float* __restrict__ hin,
                                           const float* __restrict__ Whh,
                                           int b0g, int h0g, int kbase, int nchunks,
                                           char* sm, int tid)
{
    float (*hsmb)[16][132] = (float (*)[16][132])sm;             // 2 x 8448
    float (*wsmb)[16][132] = (float (*)[16][132])(sm + 16896);   // 2 x 8448

    const int tx = tid & 15;
    const int ty = tid >> 4;
    const int r0 = tid >> 2,          kq0 = (tid & 3) * 4;
    const int r1 = (tid + 256) >> 2,  kq1 = ((tid + 256) & 3) * 4;
    const int wrow0 = (r0 >> 5) * H_ + h0g + (r0 & 31);
    const int wrow1 = (r1 >> 5) * H_ + h0g + (r1 & 31);
    const float4* hb0 = (const float4*)(hin + (size_t)(b0g + r0) * H_ + kbase + kq0);
    const float4* hb1 = (const float4*)(hin + (size_t)(b0g + r1) * H_ + kbase + kq1);
    const float4* wb0 = (const float4*)(Whh + (size_t)wrow0 * H_ + kbase + kq0);
    const float4* wb1 = (const float4*)(Whh + (size_t)wrow1 * H_ + kbase + kq1);

    // prologue: fill buffer 0
    {
        const float4 ph0 = __ldcg(hb0);
        const float4 ph1 = __ldcg(hb1);
        const float4 pw0 = __ldg(wb0);
        const float4 pw1 = __ldg(wb1);
        hsmb[0][kq0 + 0][r0] = ph0.x; hsmb[0][kq0 + 1][r0] = ph0.y;
        hsmb[0][kq0 + 2][r0] = ph0.z; hsmb[0][kq0 + 3][r0] = ph0.w;
        hsmb[0][kq1 + 0][r1] = ph1.x; hsmb[0][kq1 + 1][r1] = ph1.y;
        hsmb[0][kq1 + 2][r1] = ph1.z; hsmb[0][kq1 + 3][r1] = ph1.w;
        wsmb[0][kq0 + 0][r0] = pw0.x; wsmb[0][kq0 + 1][r0] = pw0.y;
        wsmb[0][kq0 + 2][r0] = pw0.z; wsmb[0][kq0 + 3][r0] = pw0.w;
        wsmb[0][kq1 + 0][r1] = pw1.x; wsmb[0][kq1 + 1][r1] = pw1.y;
        wsmb[0][kq1 + 2][r1] = pw1.z; wsmb[0][kq1 + 3][r1] = pw1.w;
    }
    __syncthreads();

    for (int c = 0; c < nchunks; c++) {
        const int cur = c & 1;
        float4 nh0, nh1, nw0, nw1;
        const bool hasNext = (c + 1 < nchunks);
        if (hasNext) {
            nh0 = __ldcg(hb0 + (c + 1) * 4);
            nh1 = __ldcg(hb1 + (c + 1) * 4);
            nw0 = __ldg(wb0 + (c + 1) * 4);
            nw1 = __ldg(wb1 + (c + 1) * 4);
        }

#pragma unroll
        for (int kk = 0; kk < 16; kk++) {
            const float4 a0 = *(const float4*)&hsmb[cur][kk][ty * 8];
            const float4 a1 = *(const float4*)&hsmb[cur][kk][ty * 8 + 4];
            const ull w0 = *(const ull*)&wsmb[cur][kk][      tx * 2];
            const ull w1 = *(const ull*)&wsmb[cur][kk][32  + tx * 2];
            const ull w2 = *(const ull*)&wsmb[cur][kk][64  + tx * 2];
            const ull w3 = *(const ull*)&wsmb[cur][kk][96  + tx * 2];
            const float hv[8] = {a0.x, a0.y, a0.z, a0.w, a1.x, a1.y, a1.z, a1.w};
#pragma unroll
            for (int u = 0; u < 8; u++) {
                const ull h2 = dup2(hv[u]);
                ffma2(acc2[u][0], h2, w0);
                ffma2(acc2[u][1], h2, w1);
                ffma2(acc2[u][2], h2, w2);
                ffma2(acc2[u][3], h2, w3);
            }
        }

        if (hasNext) {
            const int nxt = cur ^ 1;
            hsmb[nxt][kq0 + 0][r0] = nh0.x; hsmb[nxt][kq0 + 1][r0] = nh0.y;
            hsmb[nxt][kq0 + 2][r0] = nh0.z; hsmb[nxt][kq0 + 3][r0] = nh0.w;
            hsmb[nxt][kq1 + 0][r1] = nh1.x; hsmb[nxt][kq1 + 1][r1] = nh1.y;
            hsmb[nxt][kq1 + 2][r1] = nh1.z; hsmb[nxt][kq1 + 3][r1] = nh1.w;
            wsmb[nxt][kq0 + 0][r0] = nw0.x; wsmb[nxt][kq0 + 1][r0] = nw0.y;
            wsmb[nxt][kq0 + 2][r0] = nw0.z; wsmb[nxt][kq0 + 3][r0] = nw0.w;
            wsmb[nxt][kq1 + 0][r1] = nw1.x; wsmb[nxt][kq1 + 1][r1] = nw1.y;
            wsmb[nxt][kq1 + 2][r1] = nw1.z; wsmb[nxt][kq1 + 3][r1] = nw1.w;
        }
        __syncthreads();
    }
}

// ---------------------------------------------------------------------------
// init / transposes
// ---------------------------------------------------------------------------
__global__ void init_kernel(const float* __restrict__ input,
                            const float* __restrict__ onehots,
                            const float* __restrict__ Wh, const float* __restrict__ bh,
                            const float* __restrict__ Wc, const float* __restrict__ bc,
                            const float* __restrict__ b_ih, const float* __restrict__ b_hh)
{
    const int b = blockIdx.x;
    const int tid = threadIdx.x;
    const float xv = input[b];

    if (b == 0 && tid == 0) {
        d_bar_count = 0; d_bar_gen = 0; d_tok_cnt = 0; d_tok_gen = 0;
    }
    if (tid == 0 && b < NGATES) d_pflag[b] = 0;
    for (int i = tid; i < H_; i += 256) {
        d_hbuf[0][b * H_ + i] = xv * Wh[i] + bh[i];
        d_c[b * H_ + i]       = xv * Wc[i] + bc[i];
    }
    if (b < H4_ / 256) {
        const int j = b * 256 + tid;
        d_bias[j] = b_ih[j] + b_hh[j];
    }
    const float* oh = onehots + (size_t)b * T_ * V_;
    for (int v = tid; v < V_; v += 256)
        if (oh[v] > 0.5f) d_tok[b] = v;
}

__global__ void transpose_w2_kernel(const float* __restrict__ W2)
{
    const int k = blockIdx.x;
    for (int v = threadIdx.x; v < V_; v += 256)
        d_W2T[k * V_ + v] = __ldg(&W2[(size_t)v * GEN_ + k]);
}

__global__ void transpose_wih_kernel(const float* __restrict__ Wih)
{
    __shared__ float tile[32][33];
    const int j0 = blockIdx.x * 32;
    const int v0 = blockIdx.y * 32;
    const int tx = threadIdx.x & 31;
    const int ty = threadIdx.x >> 5;
    for (int r = ty; r < 32; r += 8)
        tile[r][tx] = Wih[(size_t)(j0 + r) * V_ + v0 + tx];
    __syncthreads();
    for (int r = ty; r < 32; r += 8)
        d_WihT[(size_t)(v0 + r) * H4_ + j0 + tx] = tile[tx][r];
}

// ---------------------------------------------------------------------------
// Pipelined persistent kernel with K-split cooperation.
// Blocks 0..127 (gates): k in [0,384) + cell epilogue (merges partner partial).
// Blocks 128..255 (head): head phases, then k in [384,512) partial for the
// SAME tile index, published via d_part/d_pflag.
// ---------------------------------------------------------------------------
extern __shared__ __align__(1024) char smemc[];

__global__ void __launch_bounds__(256, 2)
lstm_pipeline_kernel(const float* __restrict__ Whh,
                     const float* __restrict__ W1, const float* __restrict__ b1,
                     const float* __restrict__ b2, float* __restrict__ out)
{
    const int tid = threadIdx.x;
    const int blk = blockIdx.x;

    if (blk < NGATES) {
        // ==================== GATES ROLE ====================
        const int b0g = (blk & 7) * 128;
        const int h0g = (blk >> 3) * 32;
        const int tx = tid & 15;
        const int ty = tid >> 4;
        int* tok_s = (int*)(smemc + SM_TOK);

        // hoisted bias (constant across steps)
        const int hbase = h0g + tx * 2;
        float bb[8];
#pragma unroll
        for (int q = 0; q < 4; q++) {
            bb[q * 2 + 0] = d_bias[q * H_ + hbase + 0];
            bb[q * 2 + 1] = d_bias[q * H_ + hbase + 1];
        }
        const ull* pbase = (const ull*)d_part + (size_t)blk * 8192;

        for (int t = 0; t < T_; t++) {
            const int par = t & 1;
            float* hout = d_hbuf[par ^ 1];

            ull acc2[8][4];
#pragma unroll
            for (int u = 0; u < 8; u++)
#pragma unroll
                for (int j = 0; j < 4; j++) acc2[u][j] = 0ull;

            gemm_slice(acc2, d_hbuf[par], Whh, b0g, h0g, 0, NCH_G, smemc, tid);

            // wait partner partial + tok
            if (tid == 0) {
                while (((volatile unsigned*)d_pflag)[blk] < (unsigned)(t + 1)) { __nanosleep(32); }
                if (t > 0) {
                    while (*((volatile unsigned*)&d_tok_gen) < (unsigned)t) { __nanosleep(32); }
                }
            }
            __syncthreads();
            if (tid < 128) tok_s[tid] = __ldcg(&d_tok[b0g + tid]);
            __syncthreads();

            // fused LSTM cell epilogue (merge K-partial + WihT gather)
#pragma unroll
            for (int u = 0; u < 8; u++) {
                const int b = b0g + ty * 8 + u;
                const int tok = tok_s[ty * 8 + u];
                const float* WT = d_WihT + (size_t)tok * H4_;
                const float2 wi0 = __ldcg((const float2*)&WT[0 * H_ + hbase]);
                const float2 wi1 = __ldcg((const float2*)&WT[1 * H_ + hbase]);
                const float2 wi2 = __ldcg((const float2*)&WT[2 * H_ + hbase]);
                const float2 wi3 = __ldcg((const float2*)&WT[3 * H_ + hbase]);
                const int pidx = (ty * 8 + u) * 64 + tx;
                const float2 p0 = unp2(__ldcg(&pbase[pidx + 0 * 16]));
                const float2 p1 = unp2(__ldcg(&pbase[pidx + 1 * 16]));
                const float2 p2 = unp2(__ldcg(&pbase[pidx + 2 * 16]));
                const float2 p3 = unp2(__ldcg(&pbase[pidx + 3 * 16]));
                const float2 cold = *(const float2*)&d_c[b * H_ + hbase];
                const float2 g0 = unp2(acc2[u][0]);
                const float2 g1 = unp2(acc2[u][1]);
                const float2 g2 = unp2(acc2[u][2]);
                const float2 g3 = unp2(acc2[u][3]);
                float2 cnew, hnew;
                {
                    const float gi = g0.x + p0.x + wi0.x + bb[0];
                    const float gf = g1.x + p1.x + wi1.x + bb[2];
                    const float gg = g2.x + p2.x + wi2.x + bb[4];
                    const float go = g3.x + p3.x + wi3.x + bb[6];
                    const float cn = sigm(gf) * cold.x + sigm(gi) * tanhf(gg);
                    cnew.x = cn; hnew.x = sigm(go) * tanhf(cn);
                }
                {
                    const float gi = g0.y + p0.y + wi0.y + bb[1];
                    const float gf = g1.y + p1.y + wi1.y + bb[3];
                    const float gg = g2.y + p2.y + wi2.y + bb[5];
                    const float go = g3.y + p3.y + wi3.y + bb[7];
                    const float cn = sigm(gf) * cold.y + sigm(gi) * tanhf(gg);
                    cnew.y = cn; hnew.y = sigm(go) * tanhf(cn);
                }
                *(float2*)&d_c[b * H_ + hbase]  = cnew;
                *(float2*)&hout[b * H_ + hbase] = hnew;
            }
            stage_barrier();
        }
        stage_barrier();   // match head's stage-0 barrier

    } else {
        // ==================== HEAD ROLE ====================
        float* sbuf = (float*)smemc;                            // 8x1024 (h, then z2)
        float2 (*z1d)[104] = (float2 (*)[104])(smemc + SMH_Z1D);
        float* lse_s = (float*)(smemc + SMH_LSE);

        const int hid = blk - NGATES;
        const int b0h = hid * 8;
        const int w = tid >> 5, lane = tid & 31;
        // partner-tile coords for the K-partial
        const int pb0g = (hid & 7) * 128;
        const int ph0g = (hid >> 3) * 32;
        const int ptx = tid & 15, pty = tid >> 4;
        ull* pout = (ull*)d_part + (size_t)hid * 8192;

        // ---- stage 0: partial for gates step 0 ----
        {
            ull acc2[8][4];
#pragma unroll
            for (int u = 0; u < 8; u++)
#pragma unroll
                for (int j = 0; j < 4; j++) acc2[u][j] = 0ull;
            gemm_slice(acc2, d_hbuf[0], Whh, pb0g, ph0g, KSPLIT, NCH_H, smemc, tid);
#pragma unroll
            for (int u = 0; u < 8; u++)
#pragma unroll
                for (int j = 0; j < 4; j++)
                    pout[(pty * 8 + u) * 64 + j * 16 + ptx] = acc2[u][j];
            __threadfence();
            __syncthreads();
            if (tid == 0) ((volatile unsigned*)d_pflag)[hid] = 1u;
        }
        stage_barrier();

        for (int t = 0; t < T_; t++) {
            const float* __restrict__ hbuf = d_hbuf[(t + 1) & 1];

            {
                float4* sb4 = (float4*)sbuf;
                const float4* hb4 = (const float4*)(hbuf + (size_t)b0h * H_);
                for (int i = tid; i < 8 * H_ / 4; i += 256) sb4[i] = __ldcg(hb4 + i);
            }
            __syncthreads();

            // z1: warp per output column g
            for (int g = w; g < GEN_; g += 8) {
                float a[8];
#pragma unroll
                for (int bi = 0; bi < 8; bi++) a[bi] = 0.f;
                const float4* wp = (const float4*)(W1 + (size_t)g * H_);
#pragma unroll
                for (int p = 0; p < 4; p++) {
                    const float4 wv = __ldg(wp + p * 32 + lane);
#pragma unroll
                    for (int bi = 0; bi < 8; bi++) {
                        const float4 hv = *(const float4*)&sbuf[bi * H_ + (p * 32 + lane) * 4];
                        a[bi] += wv.x * hv.x + wv.y * hv.y + wv.z * hv.z + wv.w * hv.w;
                    }
                }
#pragma unroll
                for (int bi = 0; bi < 8; bi++) {
#pragma unroll
                    for (int off = 16; off; off >>= 1)
                        a[bi] += __shfl_down_sync(0xffffffffu, a[bi], off);
                }
                if (lane == 0) {
                    const float bv = b1[g];
#pragma unroll
                    for (int bi = 0; bi < 8; bi++) {
                        const float z = fmaxf(a[bi] + bv, 0.f);
                        z1d[bi][g] = make_float2(z, z);
                    }
                }
            }
            __syncthreads();

            // z2: thread owns 4 consecutive v; coalesced W2T rows; FFMA2
            float (*z2s)[1024] = (float (*)[1024])sbuf;
            {
                const int v0 = tid * 4;
                ull acc[8][2];
                {
                    const float4 bv = *(const float4*)(b2 + v0);
                    const ull bl = pack2(bv.x, bv.y), bh2 = pack2(bv.z, bv.w);
#pragma unroll
                    for (int bi = 0; bi < 8; bi++) { acc[bi][0] = bl; acc[bi][1] = bh2; }
                }
#pragma unroll 5
                for (int k = 0; k < GEN_; k++) {
                    const float4 wv = __ldcg((const float4*)(d_W2T + k * V_ + v0));
                    const ull wl = pack2(wv.x, wv.y), wh = pack2(wv.z, wv.w);
#pragma unroll
                    for (int bi = 0; bi < 8; bi++) {
                        const ull z = *(const ull*)&z1d[bi][k];
                        ffma2(acc[bi][0], z, wl);
                        ffma2(acc[bi][1], z, wh);
                    }
                }
#pragma unroll
                for (int bi = 0; bi < 8; bi++) {
                    const float2 lo = unp2(acc[bi][0]);
                    const float2 hi = unp2(acc[bi][1]);
                    *(float4*)&z2s[bi][v0] = make_float4(lo.x, lo.y, hi.x, hi.y);
                }
            }
            __syncthreads();

            // argmax + LSE; publish tok ASAP
            {
                float m = -3.0e38f; int mi = 0;
                for (int v = lane; v < V_; v += 32) {
                    const float x = z2s[w][v];
                    if (x > m) { m = x; mi = v; }
                }
#pragma unroll
                for (int off = 16; off; off >>= 1) {
                    const float om  = __shfl_down_sync(0xffffffffu, m, off);
                    const int   omi = __shfl_down_sync(0xffffffffu, mi, off);
                    if (om > m || (om == m && omi < mi)) { m = om; mi = omi; }
                }
                m  = __shfl_sync(0xffffffffu, m, 0);
                mi = __shfl_sync(0xffffffffu, mi, 0);

                float s = 0.f;
                for (int v = lane; v < V_; v += 32) s += expf(z2s[w][v] - m);
#pragma unroll
                for (int off = 16; off; off >>= 1) s += __shfl_down_sync(0xffffffffu, s, off);

                if (lane == 0) {
                    lse_s[w] = m + logf(s);
                    d_tok[b0h + w] = mi;
                }
            }
            __syncthreads();
            __threadfence();
            if (tid == 0) {
                if (atomicAdd(&d_tok_cnt, 1u) == NHEAD - 1) {
                    d_tok_cnt = 0;
                    __threadfence();
                    *((volatile unsigned*)&d_tok_gen) = (unsigned)(t + 1);
                }
            }

            // output writes
            float* orow = out + (size_t)t * B_ * V_ + (size_t)b0h * V_;
            for (int i = tid; i < 8 * V_ / 4; i += 256) {
                const int bi = i >> 8;
                float4 v4 = *(const float4*)&z2s[bi][(i & 255) * 4];
                const float l = lse_s[bi];
                v4.x -= l; v4.y -= l; v4.z -= l; v4.w -= l;
                *(float4*)&orow[i * 4] = v4;
            }

            // ---- K-partial for gates step t+1 (reads d_hbuf[(t+1)&1]) ----
            if (t < T_ - 1) {
                __syncthreads();   // z2s dead before smem reuse
                ull acc2[8][4];
#pragma unroll
                for (int u = 0; u < 8; u++)
#pragma unroll
                    for (int j = 0; j < 4; j++) acc2[u][j] = 0ull;
                gemm_slice(acc2, d_hbuf[(t + 1) & 1], Whh, pb0g, ph0g, KSPLIT, NCH_H, smemc, tid);
#pragma unroll
                for (int u = 0; u < 8; u++)
#pragma unroll
                    for (int j = 0; j < 4; j++)
                        pout[(pty * 8 + u) * 64 + j * 16 + ptx] = acc2[u][j];
                __threadfence();
                __syncthreads();
                if (tid == 0) ((volatile unsigned*)d_pflag)[hid] = (unsigned)(t + 2);
            }
            stage_barrier();
        }
    }
}

// ---------------------------------------------------------------------------
// kernel_launch: init + 2 transposes + persistent loop
// ---------------------------------------------------------------------------
extern "C" void kernel_launch(void* const* d_in, const int* in_sizes, int n_in,
                              void* d_out, int out_size)
{
    const float* input   = (const float*)d_in[0];
    const float* onehots = (const float*)d_in[1];
    const float* Wh   = (const float*)d_in[4];
    const float* bh   = (const float*)d_in[5];
    const float* Wc   = (const float*)d_in[6];
    const float* bc   = (const float*)d_in[7];
    const float* W_ih = (const float*)d_in[8];
    const float* W_hh = (const float*)d_in[9];
    const float* b_ih = (const float*)d_in[10];
    const float* b_hh = (const float*)d_in[11];
    const float* W1   = (const float*)d_in[12];
    const float* b1   = (const float*)d_in[13];
    const float* W2   = (const float*)d_in[14];
    const float* b2   = (const float*)d_in[15];
    float* out = (float*)d_out;

    cudaFuncSetAttribute(lstm_pipeline_kernel,
                         cudaFuncAttributeMaxDynamicSharedMemorySize, SMEM_DYN);

    init_kernel<<<B_, 256>>>(input, onehots, Wh, bh, Wc, bc, b_ih, b_hh);
    transpose_w2_kernel<<<GEN_, 256>>>(W2);
    {
        dim3 g(H4_ / 32, V_ / 32);
        transpose_wih_kernel<<<g, 256>>>(W_ih);
    }
    lstm_pipeline_kernel<<<NTOT, 256, SMEM_DYN>>>(W_hh, W1, b1, b2, out);
}